// round 4
// baseline (speedup 1.0000x reference)
#include <cuda_runtime.h>
#include <cstdint>

#define OPT 64
#define DIN 128
#define DOUT 128
#define TILE_M 64
#define MAX_B 16384
#define HBLK 64                               // histogram blocks (B/256)
#define MAX_TILES (MAX_B / TILE_M + OPT)      // 320

// Scratch (device allocation is banned)
__device__ int g_blockhist[HBLK][OPT];
__device__ int g_expert_end[OPT];
__device__ int g_rowids[MAX_B];
__device__ int g_ntiles;
__device__ int g_tile_e[MAX_TILES];
__device__ int g_tile_m0[MAX_TILES];

// ---------------- Kernel 1: per-block histogram (smem atomics only) ----------------

__global__ void hist_kernel(const int* __restrict__ idx, int B) {
    __shared__ int h[OPT];
    int t = threadIdx.x;
    if (t < OPT) h[t] = 0;
    __syncthreads();
    int i = blockIdx.x * 256 + t;
    if (i < B) {
        int e = idx[i];
        if (e >= 0 && e < OPT) atomicAdd(&h[e], 1);
    }
    __syncthreads();
    if (t < OPT) g_blockhist[blockIdx.x][t] = h[t];
}

// ---------------- Kernel 2: scan (redundant per block) + scatter + tile list ----------------

__global__ void scatter_kernel(const int* __restrict__ idx, int B) {
    __shared__ int part[4][OPT];   // group-of-16-blocks partial totals
    __shared__ int stot[OPT], spre[OPT], soff[OPT], sbase[OPT], cur[OPT];
    int t = threadIdx.x;
    int nblk = (B + 255) / 256;

    {   // partial sums over 16-block groups
        int e = t & 63, g = t >> 6;
        int s = 0;
        #pragma unroll
        for (int b = g * 16; b < g * 16 + 16; b++)
            s += (b < nblk) ? g_blockhist[b][e] : 0;
        part[g][e] = s;
    }
    __syncthreads();
    if (t < OPT) {
        int e = t;
        int tot = part[0][e] + part[1][e] + part[2][e] + part[3][e];
        int pre = 0;
        int full = blockIdx.x >> 4;
        for (int g = 0; g < full; g++) pre += part[g][e];
        for (int b = full * 16; b < (int)blockIdx.x; b++) pre += g_blockhist[b][e];
        stot[e] = tot; spre[e] = pre;
    }
    __syncthreads();
    if (t == 0) {
        int a = 0;
        for (int e = 0; e < OPT; e++) { soff[e] = a; a += stot[e]; }
    }
    __syncthreads();
    if (t < OPT) { sbase[t] = soff[t] + spre[t]; cur[t] = 0; }
    __syncthreads();

    // block 0 emits expert ends + tile worklist (overlaps with scatter below)
    if (blockIdx.x == 0) {
        if (t < OPT) g_expert_end[t] = soff[t] + stot[t];
        if (t == 1 % 256 || t == 1) {}  // no-op
        if (t == 0) {
            int ta = 0;
            for (int e = 0; e < OPT; e++) {
                int nt = (stot[e] + TILE_M - 1) / TILE_M;
                for (int i = 0; i < nt; i++) {
                    g_tile_e[ta] = e;
                    g_tile_m0[ta] = soff[e] + i * TILE_M;
                    ta++;
                }
            }
            g_ntiles = ta;
        }
    }

    int i = blockIdx.x * 256 + t;
    if (i < B) {
        int e = idx[i];
        if (e >= 0 && e < OPT) {
            int r = atomicAdd(&cur[e], 1);               // smem atomic only
            g_rowids[sbase[e] + r] = i;                  // order within expert is free
        }
    }
}

// ---------------- Kernel 3: compute, one block per (expert, 64-row) tile ----------------
// 256 threads: thread = (rg 0..15) x (cg 0..15); each owns 4 rows x 8 cols, packed f32x2.

#define NT 256
#define SMEM_BYTES (DIN * DOUT * 4 + TILE_M * DIN * 4 + TILE_M * 4)

__device__ __forceinline__ unsigned long long ffma2(unsigned long long a,
                                                    unsigned long long b,
                                                    unsigned long long c) {
    unsigned long long d;
    asm("fma.rn.f32x2 %0, %1, %2, %3;" : "=l"(d) : "l"(a), "l"(b), "l"(c));
    return d;
}

__device__ __forceinline__ unsigned long long dup2(float v) {
    unsigned long long d;
    asm("mov.b64 %0, {%1, %1};" : "=l"(d) : "f"(v));
    return d;
}

__global__ __launch_bounds__(NT, 2)
void mm_kernel(const float* __restrict__ x, const float* __restrict__ w,
               const float* __restrict__ bias, float* __restrict__ out) {
    int tile = blockIdx.x;
    if (tile >= g_ntiles) return;
    int e = g_tile_e[tile];
    int m0 = g_tile_m0[tile];
    int mcnt = min(TILE_M, g_expert_end[e] - m0);

    extern __shared__ float smem[];
    float* sw = smem;                       // [DIN][DOUT] k-major, 64 KB
    float* sx = smem + DIN * DOUT;          // [TILE_M][DIN], 32 KB
    int* srow = (int*)(sx + TILE_M * DIN);  // [TILE_M]

    int t = threadIdx.x;

    // Stage w[e] (coalesced float4): 4096 float4 / 256 thr = 16 iters
    {
        const float4* wg = (const float4*)(w + (size_t)e * DIN * DOUT);
        float4* swv = (float4*)sw;
        #pragma unroll
        for (int i = t; i < DIN * DOUT / 4; i += NT) swv[i] = wg[i];
    }
    // Stage gathered x rows + row ids
    for (int r = t; r < TILE_M; r += NT)
        srow[r] = (r < mcnt) ? g_rowids[m0 + r] : 0;
    for (int i = t; i < mcnt * (DIN / 4); i += NT) {
        int r = i >> 5;          // DIN/4 = 32 float4 per row
        int c = i & 31;
        int gr = g_rowids[m0 + r];
        ((float4*)(sx + r * DIN))[c] = ((const float4*)(x + (size_t)gr * DIN))[c];
    }
    __syncthreads();

    int cg = t & 15;    // cols [8*cg, 8*cg+8)
    int rg = t >> 4;    // rows [4*rg, 4*rg+4)

    // Accumulators start at bias
    unsigned long long acc[4][4];
    {
        const ulonglong2* bv = (const ulonglong2*)(bias + (size_t)e * DOUT + 8 * cg);
        ulonglong2 b01 = bv[0];
        ulonglong2 b23 = bv[1];
        #pragma unroll
        for (int r = 0; r < 4; r++) {
            acc[r][0] = b01.x; acc[r][1] = b01.y;
            acc[r][2] = b23.x; acc[r][3] = b23.y;
        }
    }

    const float4* sx4 = (const float4*)(sx + (rg * 4) * DIN);  // row r at +r*32 float4
    const char* swb = (const char*)sw + 32 * cg;

    #pragma unroll 4
    for (int kc = 0; kc < DIN / 4; kc++) {
        float4 xv[4];
        #pragma unroll
        for (int r = 0; r < 4; r++) xv[r] = sx4[r * 32 + kc];
        #pragma unroll
        for (int kk = 0; kk < 4; kk++) {
            int k = kc * 4 + kk;
            ulonglong2 w01 = *(const ulonglong2*)(swb + (size_t)k * DOUT * 4);
            ulonglong2 w23 = *(const ulonglong2*)(swb + (size_t)k * DOUT * 4 + 16);
            #pragma unroll
            for (int r = 0; r < 4; r++) {
                unsigned long long xx = dup2(((const float*)&xv[r])[kk]);
                acc[r][0] = ffma2(xx, w01.x, acc[r][0]);
                acc[r][1] = ffma2(xx, w01.y, acc[r][1]);
                acc[r][2] = ffma2(xx, w23.x, acc[r][2]);
                acc[r][3] = ffma2(xx, w23.y, acc[r][3]);
            }
        }
    }

    // Writeback (two STG.128 per live row)
    #pragma unroll
    for (int r = 0; r < 4; r++) {
        int row = rg * 4 + r;
        if (row < mcnt) {
            int gr = srow[row];
            ulonglong2* o = (ulonglong2*)(out + (size_t)gr * DOUT + 8 * cg);
            o[0] = make_ulonglong2(acc[r][0], acc[r][1]);
            o[1] = make_ulonglong2(acc[r][2], acc[r][3]);
        }
    }
}

extern "C" void kernel_launch(void* const* d_in, const int* in_sizes, int n_in,
                              void* d_out, int out_size) {
    const float* x = (const float*)d_in[0];
    const float* w = (const float*)d_in[1];
    const float* b = (const float*)d_in[2];
    const int* idx = (const int*)d_in[3];   // JAX x64-disabled: indices arrive int32
    float* out = (float*)d_out;
    int B = in_sizes[3];
    if (B > MAX_B) B = MAX_B;

    cudaFuncSetAttribute(mm_kernel, cudaFuncAttributeMaxDynamicSharedMemorySize,
                         SMEM_BYTES);

    int nblk = (B + 255) / 256;
    hist_kernel<<<nblk, 256>>>(idx, B);
    scatter_kernel<<<nblk, 256>>>(idx, B);
    mm_kernel<<<MAX_TILES, NT, SMEM_BYTES>>>(x, w, b, out);
}

// round 5
// speedup vs baseline: 1.4594x; 1.4594x over previous
#include <cuda_runtime.h>
#include <cstdint>

#define OPT 64
#define DIN 128
#define DOUT 128
#define TILE_M 64
#define MAX_B 16384
#define HBLK 16                               // histogram blocks (B/1024)
#define MAX_TILES (MAX_B / TILE_M + OPT)      // 320

// Scratch (device allocation is banned)
__device__ int g_blockhist[HBLK][OPT];
__device__ int g_blockbase[HBLK][OPT];
__device__ int g_expert_end[OPT];
__device__ int g_rowids[MAX_B];
__device__ int g_ntiles;
__device__ int g_tile_e[MAX_TILES];
__device__ int g_tile_m0[MAX_TILES];

// ---------------- Prelude: counting sort by expert, no global atomics ----------------
// 16 blocks x 256 threads x 4 elements (int4 loads)

__global__ void hist_kernel(const int* __restrict__ idx, int B) {
    __shared__ int h[OPT];
    int t = threadIdx.x;
    if (t < OPT) h[t] = 0;
    __syncthreads();
    int i4 = blockIdx.x * 256 + t;
    if (i4 * 4 + 3 < B) {
        int4 v = ((const int4*)idx)[i4];
        if (v.x >= 0 && v.x < OPT) atomicAdd(&h[v.x], 1);
        if (v.y >= 0 && v.y < OPT) atomicAdd(&h[v.y], 1);
        if (v.z >= 0 && v.z < OPT) atomicAdd(&h[v.z], 1);
        if (v.w >= 0 && v.w < OPT) atomicAdd(&h[v.w], 1);
    } else {
        for (int i = i4 * 4; i < min(i4 * 4 + 4, B); i++) {
            int e = idx[i];
            if (e >= 0 && e < OPT) atomicAdd(&h[e], 1);
        }
    }
    __syncthreads();
    if (t < OPT) g_blockhist[blockIdx.x][t] = h[t];
}

__global__ void scan_kernel(int B) {
    __shared__ int tot[OPT];
    __shared__ int off[OPT];
    __shared__ int toff[OPT];
    int e = threadIdx.x;  // 64 threads
    int nblk = (B + 1023) / 1024;
    int s = 0;
    for (int b = 0; b < nblk; b++) s += g_blockhist[b][e];
    tot[e] = s;
    __syncthreads();
    if (e == 0) {
        int acc = 0, tacc = 0;
        for (int i = 0; i < OPT; i++) {
            off[i] = acc; acc += tot[i];
            toff[i] = tacc; tacc += (tot[i] + TILE_M - 1) / TILE_M;
        }
        g_ntiles = tacc;
    }
    __syncthreads();
    int run = off[e];
    for (int b = 0; b < nblk; b++) { g_blockbase[b][e] = run; run += g_blockhist[b][e]; }
    g_expert_end[e] = off[e] + tot[e];
    int nt = (tot[e] + TILE_M - 1) / TILE_M;
    for (int i = 0; i < nt; i++) {
        g_tile_e[toff[e] + i] = e;
        g_tile_m0[toff[e] + i] = off[e] + i * TILE_M;
    }
}

__global__ void scatter_kernel(const int* __restrict__ idx, int B) {
    __shared__ int cur[OPT];
    int t = threadIdx.x;
    if (t < OPT) cur[t] = 0;
    __syncthreads();
    int i4 = blockIdx.x * 256 + t;
    if (i4 * 4 + 3 < B) {
        int4 v = ((const int4*)idx)[i4];
        int es[4] = {v.x, v.y, v.z, v.w};
        #pragma unroll
        for (int j = 0; j < 4; j++) {
            int e = es[j];
            if (e >= 0 && e < OPT) {
                int r = atomicAdd(&cur[e], 1);
                g_rowids[g_blockbase[blockIdx.x][e] + r] = i4 * 4 + j;
            }
        }
    } else {
        for (int i = i4 * 4; i < min(i4 * 4 + 4, B); i++) {
            int e = idx[i];
            if (e >= 0 && e < OPT) {
                int r = atomicAdd(&cur[e], 1);
                g_rowids[g_blockbase[blockIdx.x][e] + r] = i;
            }
        }
    }
}

// ---------------- Compute: one block per (expert, 64-row) tile ----------------
// 128 threads; cg = t&15 owns 8 cols, rg = t>>4 owns 8 rows; packed f32x2 FFMA.

#define NT 128
#define SMEM_BYTES (DIN * DOUT * 4 + TILE_M * DIN * 4 + TILE_M * 4)

__device__ __forceinline__ unsigned long long ffma2(unsigned long long a,
                                                    unsigned long long b,
                                                    unsigned long long c) {
    unsigned long long d;
    asm("fma.rn.f32x2 %0, %1, %2, %3;" : "=l"(d) : "l"(a), "l"(b), "l"(c));
    return d;
}

__device__ __forceinline__ unsigned long long dup2(float v) {
    unsigned long long d;
    asm("mov.b64 %0, {%1, %1};" : "=l"(d) : "f"(v));
    return d;
}

__global__ __launch_bounds__(NT, 2)
void mm_kernel(const float* __restrict__ x, const float* __restrict__ w,
               const float* __restrict__ bias, float* __restrict__ out) {
    int tile = blockIdx.x;
    if (tile >= g_ntiles) return;
    int e = g_tile_e[tile];
    int m0 = g_tile_m0[tile];
    int mcnt = min(TILE_M, g_expert_end[e] - m0);

    extern __shared__ float smem[];
    float* sw = smem;                       // [DIN][DOUT] k-major, 64 KB
    float* sx = smem + DIN * DOUT;          // [TILE_M][DIN], 32 KB
    int* srow = (int*)(sx + TILE_M * DIN);  // [TILE_M]

    int t = threadIdx.x;

    // Stage w[e] (coalesced float4)
    {
        const float4* wg = (const float4*)(w + (size_t)e * DIN * DOUT);
        float4* swv = (float4*)sw;
        #pragma unroll
        for (int i = t; i < DIN * DOUT / 4; i += NT) swv[i] = wg[i];
    }
    // Stage gathered x rows + row ids
    for (int r = t; r < TILE_M; r += NT)
        srow[r] = (r < mcnt) ? g_rowids[m0 + r] : 0;
    for (int i = t; i < mcnt * (DIN / 4); i += NT) {
        int r = i >> 5;          // DIN/4 = 32 float4 per row
        int c = i & 31;
        int gr = g_rowids[m0 + r];
        ((float4*)(sx + r * DIN))[c] = ((const float4*)(x + (size_t)gr * DIN))[c];
    }
    __syncthreads();

    int cg = t & 15;    // cols [8*cg, 8*cg+8)
    int rg = t >> 4;    // rows [8*rg, 8*rg+8)

    // Accumulators start at bias (pairs of floats as packed f32x2)
    unsigned long long acc[8][4];
    {
        const ulonglong2* bv = (const ulonglong2*)(bias + (size_t)e * DOUT + 8 * cg);
        ulonglong2 b01 = bv[0];
        ulonglong2 b23 = bv[1];
        #pragma unroll
        for (int r = 0; r < 8; r++) {
            acc[r][0] = b01.x; acc[r][1] = b01.y;
            acc[r][2] = b23.x; acc[r][3] = b23.y;
        }
    }

    const float2* sx2 = (const float2*)(sx + (rg * 8) * DIN);  // row r: +r*64 float2
    const char* swb = (const char*)sw + 32 * cg;

    // k processed in chunks of 2; x for the chunk hoisted as float2 (broadcast LDS.64)
    #pragma unroll 2
    for (int kc = 0; kc < DIN / 2; kc++) {
        float2 xv[8];
        #pragma unroll
        for (int r = 0; r < 8; r++) xv[r] = sx2[r * 64 + kc];
        #pragma unroll
        for (int kk = 0; kk < 2; kk++) {
            int k = kc * 2 + kk;
            ulonglong2 w01 = *(const ulonglong2*)(swb + (size_t)k * DOUT * 4);
            ulonglong2 w23 = *(const ulonglong2*)(swb + (size_t)k * DOUT * 4 + 16);
            #pragma unroll
            for (int r = 0; r < 8; r++) {
                unsigned long long xx = dup2(kk == 0 ? xv[r].x : xv[r].y);
                acc[r][0] = ffma2(xx, w01.x, acc[r][0]);
                acc[r][1] = ffma2(xx, w01.y, acc[r][1]);
                acc[r][2] = ffma2(xx, w23.x, acc[r][2]);
                acc[r][3] = ffma2(xx, w23.y, acc[r][3]);
            }
        }
    }

    // Writeback (two STG.128 per live row)
    #pragma unroll
    for (int r = 0; r < 8; r++) {
        int row = rg * 8 + r;
        if (row < mcnt) {
            int gr = srow[row];
            ulonglong2* o = (ulonglong2*)(out + (size_t)gr * DOUT + 8 * cg);
            o[0] = make_ulonglong2(acc[r][0], acc[r][1]);
            o[1] = make_ulonglong2(acc[r][2], acc[r][3]);
        }
    }
}

extern "C" void kernel_launch(void* const* d_in, const int* in_sizes, int n_in,
                              void* d_out, int out_size) {
    const float* x = (const float*)d_in[0];
    const float* w = (const float*)d_in[1];
    const float* b = (const float*)d_in[2];
    const int* idx = (const int*)d_in[3];   // JAX x64-disabled: indices arrive int32
    float* out = (float*)d_out;
    int B = in_sizes[3];
    if (B > MAX_B) B = MAX_B;

    cudaFuncSetAttribute(mm_kernel, cudaFuncAttributeMaxDynamicSharedMemorySize,
                         SMEM_BYTES);

    int nblk = (B + 1023) / 1024;   // <= HBLK
    hist_kernel<<<nblk, 256>>>(idx, B);
    scan_kernel<<<1, 64>>>(B);
    scatter_kernel<<<nblk, 256>>>(idx, B);
    mm_kernel<<<MAX_TILES, NT, SMEM_BYTES>>>(x, w, b, out);
}